// round 3
// baseline (speedup 1.0000x reference)
#include <cuda_runtime.h>
#include <cuda_bf16.h>
#include <math.h>

// Problem constants
#define NN     8192
#define IN_F   256
#define OUT_F  128
#define ALPHA  0.2f

#define ADJ_WORDS_PER_ROW (NN / 32)   // 256

// Scratch (device globals; no allocation)
__device__ unsigned g_adj[NN * ADJ_WORDS_PER_ROW];   // 8 MB bitmask
__device__ float    g_Wh[NN * OUT_F];                // 4 MB
__device__ float    g_s1[NN];
__device__ float    g_s2[NN];

// ---------------------------------------------------------------------------
// Kernel 1: zero the adjacency bitmask (vectorized)
// ---------------------------------------------------------------------------
__global__ __launch_bounds__(256) void zero_adj_kernel() {
    int idx = blockIdx.x * blockDim.x + threadIdx.x;      // uint4 index
    const int total = (NN * ADJ_WORDS_PER_ROW) / 4;       // 524288
    if (idx < total) {
        ((uint4*)g_adj)[idx] = make_uint4(0u, 0u, 0u, 0u);
    }
}

// ---------------------------------------------------------------------------
// Kernel 2: scatter edges into the bitmask (atomicOr dedups duplicates)
// edge_index is int32 (JAX x64 is disabled by default, so jnp.int64 -> int32).
// ---------------------------------------------------------------------------
__global__ __launch_bounds__(256) void scatter_kernel(const int* __restrict__ edge_index,
                                                      int E) {
    int k = blockIdx.x * blockDim.x + threadIdx.x;
    if (k < E) {
        int src = edge_index[k]     & (NN - 1);   // row 0 (mask is identity for valid input)
        int dst = edge_index[E + k] & (NN - 1);   // row 1
        atomicOr(&g_adj[src * ADJ_WORDS_PER_ROW + (dst >> 5)], 1u << (dst & 31));
    }
}

// ---------------------------------------------------------------------------
// Kernel 3: Wh = h @ W^T + b_lin  (fused s1 = Wh.a1, s2 = Wh.a2 epilogue)
// h: [NN, IN_F], W: [OUT_F, IN_F], Wh: [NN, OUT_F]
// Block: 256 threads, tile BM=64 rows x BN=128 (all) cols, BK=32.
// Thread (tr = tid>>5 in [0,8), tc = tid&31): 8 rows x 4 cols micro-tile.
// ---------------------------------------------------------------------------
__global__ __launch_bounds__(256) void gemm_s_kernel(const float* __restrict__ h,
                                                     const float* __restrict__ W,
                                                     const float* __restrict__ b_lin,
                                                     const float* __restrict__ a) {
    const int BM = 64, BK = 32;
    __shared__ float hs[BK][BM];       // hs[k][m]
    __shared__ float ws[BK][OUT_F];    // ws[k][n]

    int row0 = blockIdx.x * BM;
    int tid  = threadIdx.x;
    int tr   = tid >> 5;   // 0..7  (warp id)
    int tc   = tid & 31;   // 0..31 (lane)

    float acc[8][4];
#pragma unroll
    for (int i = 0; i < 8; i++)
#pragma unroll
        for (int j = 0; j < 4; j++) acc[i][j] = 0.0f;

    for (int k0 = 0; k0 < IN_F; k0 += BK) {
        // load h tile: 64x32 floats = 512 float4, 2 per thread
#pragma unroll
        for (int l = 0; l < 2; l++) {
            int idx = tid + 256 * l;          // 0..511
            int m   = idx >> 3;               // 0..63
            int kq  = idx & 7;                // quad index
            float4 v = *(const float4*)&h[(row0 + m) * IN_F + k0 + kq * 4];
            hs[kq * 4 + 0][m] = v.x;
            hs[kq * 4 + 1][m] = v.y;
            hs[kq * 4 + 2][m] = v.z;
            hs[kq * 4 + 3][m] = v.w;
        }
        // load W tile: 128x32 floats = 1024 float4, 4 per thread
#pragma unroll
        for (int l = 0; l < 4; l++) {
            int idx = tid + 256 * l;          // 0..1023
            int n   = idx >> 3;               // 0..127
            int kq  = idx & 7;
            float4 v = *(const float4*)&W[n * IN_F + k0 + kq * 4];
            ws[kq * 4 + 0][n] = v.x;
            ws[kq * 4 + 1][n] = v.y;
            ws[kq * 4 + 2][n] = v.z;
            ws[kq * 4 + 3][n] = v.w;
        }
        __syncthreads();

#pragma unroll
        for (int k = 0; k < BK; k++) {
            float4 ha = *(const float4*)&hs[k][tr * 8];
            float4 hb = *(const float4*)&hs[k][tr * 8 + 4];
            float4 wb = *(const float4*)&ws[k][tc * 4];
            float ra[8] = {ha.x, ha.y, ha.z, ha.w, hb.x, hb.y, hb.z, hb.w};
            float rb[4] = {wb.x, wb.y, wb.z, wb.w};
#pragma unroll
            for (int i = 0; i < 8; i++)
#pragma unroll
                for (int j = 0; j < 4; j++)
                    acc[i][j] = fmaf(ra[i], rb[j], acc[i][j]);
        }
        __syncthreads();
    }

    // epilogue: bias, store Wh, fused s1/s2
    int col = tc * 4;
    float4 blv = *(const float4*)&b_lin[col];
    float4 a1v = *(const float4*)&a[col];
    float4 a2v = *(const float4*)&a[OUT_F + col];
    float bl[4] = {blv.x, blv.y, blv.z, blv.w};
    float a1r[4] = {a1v.x, a1v.y, a1v.z, a1v.w};
    float a2r[4] = {a2v.x, a2v.y, a2v.z, a2v.w};

#pragma unroll
    for (int i = 0; i < 8; i++) {
        int row = row0 + tr * 8 + i;
        float v0 = acc[i][0] + bl[0];
        float v1 = acc[i][1] + bl[1];
        float v2 = acc[i][2] + bl[2];
        float v3 = acc[i][3] + bl[3];
        float4 vv = make_float4(v0, v1, v2, v3);
        *(float4*)&g_Wh[row * OUT_F + col] = vv;
        float p1 = v0 * a1r[0] + v1 * a1r[1] + v2 * a1r[2] + v3 * a1r[3];
        float p2 = v0 * a2r[0] + v1 * a2r[1] + v2 * a2r[2] + v3 * a2r[3];
#pragma unroll
        for (int o = 16; o > 0; o >>= 1) {
            p1 += __shfl_xor_sync(0xffffffffu, p1, o);
            p2 += __shfl_xor_sync(0xffffffffu, p2, o);
        }
        if (tc == 0) {
            g_s1[row] = p1;
            g_s2[row] = p2;
        }
    }
}

// ---------------------------------------------------------------------------
// Reductions over a 128-thread block
// ---------------------------------------------------------------------------
__device__ __forceinline__ float blk_reduce_max(float v, float* buf) {
#pragma unroll
    for (int o = 16; o > 0; o >>= 1)
        v = fmaxf(v, __shfl_xor_sync(0xffffffffu, v, o));
    int w = threadIdx.x >> 5;
    if ((threadIdx.x & 31) == 0) buf[w] = v;
    __syncthreads();
    float r = fmaxf(fmaxf(buf[0], buf[1]), fmaxf(buf[2], buf[3]));
    __syncthreads();
    return r;
}

__device__ __forceinline__ float blk_reduce_sum(float v, float* buf) {
#pragma unroll
    for (int o = 16; o > 0; o >>= 1)
        v += __shfl_xor_sync(0xffffffffu, v, o);
    int w = threadIdx.x >> 5;
    if ((threadIdx.x & 31) == 0) buf[w] = v;
    __syncthreads();
    float r = buf[0] + buf[1] + buf[2] + buf[3];
    __syncthreads();
    return r;
}

// ---------------------------------------------------------------------------
// Kernel 4: per-row masked softmax + aggregation + ELU
// One block (128 threads) per row. Thread t covers columns [t*64, t*64+64)
// via 2 bitmask words; thread f owns output feature f during aggregation.
// ---------------------------------------------------------------------------
#define CAP 2048

__global__ __launch_bounds__(128) void attn_kernel(const float* __restrict__ b_att_p,
                                                   float* __restrict__ out) {
    __shared__ unsigned short sj[CAP];
    __shared__ float swt[CAP];
    __shared__ int   s_cnt;
    __shared__ float rbuf[4];

    int i   = blockIdx.x;
    int tid = threadIdx.x;
    float batt = *b_att_p;
    float s1i  = g_s1[i];

    uint2 wv = *(const uint2*)&g_adj[i * ADJ_WORDS_PER_ROW + tid * 2];
    unsigned long long rem = (unsigned long long)wv.x | ((unsigned long long)wv.y << 32);
    int base = tid * 64;

    // Zero-degree row: softmax of all-equal NEG_INF -> uniform over all N.
    int anyb = __syncthreads_or(rem != 0ull);
    if (!anyb) {
        float accm = 0.0f;
        for (int j = 0; j < NN; j++) accm += g_Wh[j * OUT_F + tid];
        float v = accm * (1.0f / (float)NN);
        out[i * OUT_F + tid] = (v > 0.0f) ? v : expm1f(v);
        return;
    }

    // Pass 1: row max of leaky_relu(s1[i] + s2[j] + b_att) over neighbors
    float lmax = -INFINITY;
    {
        unsigned long long m0 = rem;
        while (m0) {
            int b = __ffsll(m0) - 1;
            m0 &= m0 - 1;
            int j = base + b;
            float t = s1i + g_s2[j] + batt;
            float e = (t > 0.0f) ? t : ALPHA * t;
            lmax = fmaxf(lmax, e);
        }
    }
    float m = blk_reduce_max(lmax, rbuf);

    // Pass 2: chunked list build + weighted aggregation
    float acc  = 0.0f;   // thread tid owns output feature `tid`
    float sumw = 0.0f;

    for (;;) {
        if (tid == 0) s_cnt = 0;
        __syncthreads();

        // fill phase
        while (rem) {
            int b   = __ffsll(rem) - 1;
            int pos = atomicAdd(&s_cnt, 1);
            if (pos >= CAP) break;       // keep bit for next chunk
            rem &= rem - 1;
            int j = base + b;
            float t = s1i + g_s2[j] + batt;
            float e = (t > 0.0f) ? t : ALPHA * t;
            sj[pos]  = (unsigned short)j;
            swt[pos] = expf(e - m);
        }
        __syncthreads();
        int cnt = min(s_cnt, CAP);

        // weight sum for this chunk
        float ls = 0.0f;
        for (int k = tid; k < cnt; k += 128) ls += swt[k];
        sumw += blk_reduce_sum(ls, rbuf);

        // aggregation: coalesced gather of Wh rows
        int k = 0;
        for (; k + 4 <= cnt; k += 4) {
            int j0 = sj[k], j1 = sj[k + 1], j2 = sj[k + 2], j3 = sj[k + 3];
            float w0 = swt[k], w1 = swt[k + 1], w2 = swt[k + 2], w3 = swt[k + 3];
            float v0 = g_Wh[j0 * OUT_F + tid];
            float v1 = g_Wh[j1 * OUT_F + tid];
            float v2 = g_Wh[j2 * OUT_F + tid];
            float v3 = g_Wh[j3 * OUT_F + tid];
            acc = fmaf(w0, v0, acc);
            acc = fmaf(w1, v1, acc);
            acc = fmaf(w2, v2, acc);
            acc = fmaf(w3, v3, acc);
        }
        for (; k < cnt; k++)
            acc = fmaf(swt[k], g_Wh[sj[k] * OUT_F + tid], acc);

        // anyone with leftovers? (barrier also protects sj/swt reuse)
        if (!__syncthreads_or(rem != 0ull)) break;
    }

    float v = acc / sumw;
    out[i * OUT_F + tid] = (v > 0.0f) ? v : expm1f(v);
}

// ---------------------------------------------------------------------------
// Launch
// Inputs: 0:h [N,256] f32, 1:edge_index [2,E] i32, 2:W [128,256] f32,
//         3:b_lin [128] f32, 4:a [1,256] f32, 5:b_att [1] f32
// ---------------------------------------------------------------------------
extern "C" void kernel_launch(void* const* d_in, const int* in_sizes, int n_in,
                              void* d_out, int out_size) {
    const float* h     = (const float*)d_in[0];
    const int*   ei    = (const int*)d_in[1];
    const float* W     = (const float*)d_in[2];
    const float* b_lin = (const float*)d_in[3];
    const float* a     = (const float*)d_in[4];
    const float* b_att = (const float*)d_in[5];
    float* out = (float*)d_out;

    int E = in_sizes[1] / 2;

    // 1) zero adjacency bitmask
    {
        int total = (NN * ADJ_WORDS_PER_ROW) / 4;
        zero_adj_kernel<<<(total + 255) / 256, 256>>>();
    }
    // 2) scatter edges
    scatter_kernel<<<(E + 255) / 256, 256>>>(ei, E);
    // 3) Wh GEMM + fused s1/s2
    gemm_s_kernel<<<NN / 64, 256>>>(h, W, b_lin, a);
    // 4) sparse softmax + aggregation + ELU
    attn_kernel<<<NN, 128>>>(b_att, out);
}